// round 11
// baseline (speedup 1.0000x reference)
#include <cuda_runtime.h>
#include <cuda_bf16.h>

#define MAX_NODES   65536
#define NB          592      // 4 blocks/SM * 148 SMs, all resident
#define NT          512      // 16 warps/block
#define STREAM_WPB  14       // warps 0..13 stream; warps 14,15 gather (phase B)

__device__ float g_uscore[MAX_NODES];   // bias folded in
__device__ float g_iscore[MAX_NODES];
__device__ unsigned g_bar_count;        // monotonic across barriers AND graph replays

// Monotonic grid barrier (no reset; only relative counts -> replay-safe).
__device__ __forceinline__ void grid_barrier()
{
    __syncthreads();
    if (threadIdx.x == 0) {
        __threadfence();
        const unsigned a = atomicAdd(&g_bar_count, 1u);
        const unsigned target = (a / NB + 1u) * NB;
        volatile unsigned* vc = &g_bar_count;
        while (*vc < target) { }
        __threadfence();
    }
    __syncthreads();
}

__device__ __forceinline__ float warp_reduce(float s)
{
    #pragma unroll
    for (int o = 16; o > 0; o >>= 1)
        s += __shfl_xor_sync(0xffffffffu, s, o);
    return s;
}

// score[r] = dot(feats[r], w) + bias, 2 rows per warp-task, grid-stride.
__device__ __forceinline__ void stream_rows(const float* __restrict__ feats,
                                            const float4 w, const float bias,
                                            float* __restrict__ table,
                                            int N, int warp_id, int nwarps, int lane)
{
    const int ntask = (N + 1) >> 1;
    for (int t = warp_id; t < ntask; t += nwarps) {
        const int r0 = 2 * t;
        const int r1 = r0 + 1;
        const float4 v0 = (reinterpret_cast<const float4*>(feats) + (size_t)r0 * 32)[lane];
        float s0 = v0.x * w.x + v0.y * w.y + v0.z * w.z + v0.w * w.w;
        float s1 = 0.0f;
        if (r1 < N) {
            const float4 v1 = (reinterpret_cast<const float4*>(feats) + (size_t)r1 * 32)[lane];
            s1 = v1.x * w.x + v1.y * w.y + v1.z * w.z + v1.w * w.w;
        }
        s0 = warp_reduce(s0);
        s1 = warp_reduce(s1);
        if (lane == 0) {
            table[r0] = s0 + bias;
            if (r1 < N) table[r1] = s1 + bias;
        }
    }
}

__global__ __launch_bounds__(NT, 4)
void fused_kernel(const float* __restrict__ user_feats,
                  const float* __restrict__ item_feats,
                  const int*   __restrict__ src_idx,
                  const int*   __restrict__ dst_idx,
                  const float* __restrict__ W,
                  const float* __restrict__ b,
                  float* __restrict__ out,
                  int Nu, int Ni, int E)
{
    const int wib  = threadIdx.x >> 5;          // 0..15
    const int lane = threadIdx.x & 31;
    const int E2   = E >> 1;

    const float4 wu = reinterpret_cast<const float4*>(W)[lane];        // W[0:128]
    const float4 wi = (reinterpret_cast<const float4*>(W) + 32)[lane]; // W[128:256]
    const float bias = b[0];

    // ---- Phase A: u-scores, all warps (DRAM-bound) -----------------------
    stream_rows(user_feats, wu, bias, g_uscore,
                Nu, blockIdx.x * 16 + wib, NB * 16, lane);
    grid_barrier();

    // ---- Phase B: warp split inside every block --------------------------
    if (wib < STREAM_WPB) {
        // i-scores on 14/16 warps (DRAM-bound).
        stream_rows(item_feats, wi, 0.0f, g_iscore,
                    Ni, blockIdx.x * STREAM_WPB + wib, NB * STREAM_WPB, lane);
    } else {
        // u-gathers -> out[e] = u[src[e]] on 2/16 warps (L1tex-bound).
        // Hides completely under the concurrent i-feature stream.
        const int gtid = (blockIdx.x * 2 + (wib - STREAM_WPB)) * 32 + lane;
        const int gnt  = NB * 2 * 32;
        const int2* s2 = reinterpret_cast<const int2*>(src_idx);
        float2*     o2 = reinterpret_cast<float2*>(out);
        for (int i = gtid; i < E2; i += gnt) {
            const int2 s = s2[i];
            float2 r;
            r.x = g_uscore[s.x];
            r.y = g_uscore[s.y];
            o2[i] = r;
        }
        if (gtid == 0 && (E & 1))
            out[E - 1] = g_uscore[src_idx[E - 1]];
    }
    grid_barrier();

    // ---- Phase C: all warps RMW out[e] += i[dst[e]] -----------------------
    {
        const int tid = blockIdx.x * NT + threadIdx.x;   // 303k threads >= E2
        const int2* d2 = reinterpret_cast<const int2*>(dst_idx);
        float2*     o2 = reinterpret_cast<float2*>(out);
        if (tid < E2) {
            const int2 d = d2[tid];
            float2 r = o2[tid];
            r.x += g_iscore[d.x];
            r.y += g_iscore[d.y];
            o2[tid] = r;
        }
        if (tid == 0 && (E & 1))
            out[E - 1] += g_iscore[dst_idx[E - 1]];
    }
}

// ---------------------------------------------------------------------------
// Inputs (metadata order): user_feats f32 [Nu,128], item_feats f32 [Ni,128],
// src_idx i32 [E], dst_idx i32 [E], W f32 [256,1], b f32 [1].
// Output: f32 [E,1].
// ---------------------------------------------------------------------------
extern "C" void kernel_launch(void* const* d_in, const int* in_sizes, int n_in,
                              void* d_out, int out_size)
{
    const float* user_feats = (const float*)d_in[0];
    const float* item_feats = (const float*)d_in[1];
    const int*   src_idx    = (const int*)d_in[2];
    const int*   dst_idx    = (const int*)d_in[3];
    const float* W          = (const float*)d_in[4];
    const float* b          = (const float*)d_in[5];
    float*       out        = (float*)d_out;

    const int Nu = in_sizes[0] / 128;
    const int Ni = in_sizes[1] / 128;
    const int E  = in_sizes[2];

    fused_kernel<<<NB, NT>>>(user_feats, item_feats, src_idx, dst_idx,
                             W, b, out, Nu, Ni, E);
}

// round 13
// speedup vs baseline: 1.1335x; 1.1335x over previous
#include <cuda_runtime.h>
#include <cuda_bf16.h>

#define MAX_NODES 65536
__device__ float g_uscore[MAX_NODES];   // bias folded in
__device__ float g_iscore[MAX_NODES];

// ---------------------------------------------------------------------------
// Node streaming: 4 rows per warp (4 independent float4 streams per lane).
// After the 4 interleaved butterfly reductions, every lane holds all four
// sums, so lane 0 writes all 4 results (NO conditional shuffles — a partial-
// warp full-mask shuffle deadlocks sm_103a; that was the R12 hang).
// ---------------------------------------------------------------------------
template <bool ADD_BIAS>
__device__ __forceinline__ void stream_rows4(const float* __restrict__ feats,
                                             const float4 w, const float bias,
                                             float* __restrict__ table,
                                             int N, int warp_id, int nwarps, int lane)
{
    const int ntask = (N + 3) >> 2;
    for (int t = warp_id; t < ntask; t += nwarps) {
        const int r0 = 4 * t;
        const float4* base = reinterpret_cast<const float4*>(feats) + (size_t)r0 * 32;

        float s0, s1, s2, s3;
        if (r0 + 3 < N) {
            const float4 v0 = base[lane];
            const float4 v1 = base[32 + lane];
            const float4 v2 = base[64 + lane];
            const float4 v3 = base[96 + lane];
            s0 = v0.x * w.x + v0.y * w.y + v0.z * w.z + v0.w * w.w;
            s1 = v1.x * w.x + v1.y * w.y + v1.z * w.z + v1.w * w.w;
            s2 = v2.x * w.x + v2.y * w.y + v2.z * w.z + v2.w * w.w;
            s3 = v3.x * w.x + v3.y * w.y + v3.z * w.z + v3.w * w.w;
        } else {
            s0 = s1 = s2 = s3 = 0.0f;
            if (r0 + 0 < N) { const float4 v = base[     lane]; s0 = v.x*w.x + v.y*w.y + v.z*w.z + v.w*w.w; }
            if (r0 + 1 < N) { const float4 v = base[32 + lane]; s1 = v.x*w.x + v.y*w.y + v.z*w.z + v.w*w.w; }
            if (r0 + 2 < N) { const float4 v = base[64 + lane]; s2 = v.x*w.x + v.y*w.y + v.z*w.z + v.w*w.w; }
            if (r0 + 3 < N) { const float4 v = base[96 + lane]; s3 = v.x*w.x + v.y*w.y + v.z*w.z + v.w*w.w; }
        }

        // 4 interleaved full-warp butterfly reductions (all lanes participate).
        #pragma unroll
        for (int o = 16; o > 0; o >>= 1) {
            s0 += __shfl_xor_sync(0xffffffffu, s0, o);
            s1 += __shfl_xor_sync(0xffffffffu, s1, o);
            s2 += __shfl_xor_sync(0xffffffffu, s2, o);
            s3 += __shfl_xor_sync(0xffffffffu, s3, o);
        }

        if (lane == 0) {
            if (ADD_BIAS) { s0 += bias; s1 += bias; s2 += bias; s3 += bias; }
            table[r0] = s0;
            if (r0 + 1 < N) table[r0 + 1] = s1;
            if (r0 + 2 < N) table[r0 + 2] = s2;
            if (r0 + 3 < N) table[r0 + 3] = s3;
        }
    }
}

__global__ void node_u_kernel(const float* __restrict__ feats,
                              const float* __restrict__ W,
                              const float* __restrict__ b, int N)
{
    const int warp = blockIdx.x * (blockDim.x >> 5) + (threadIdx.x >> 5);
    const int lane = threadIdx.x & 31;
    const int nwarps = gridDim.x * (blockDim.x >> 5);
    const float4 w = reinterpret_cast<const float4*>(W)[lane];          // W[0:128]
    stream_rows4<true>(feats, w, b[0], g_uscore, N, warp, nwarps, lane);
}

__global__ void node_i_kernel(const float* __restrict__ feats,
                              const float* __restrict__ W, int N)
{
    const int warp = blockIdx.x * (blockDim.x >> 5) + (threadIdx.x >> 5);
    const int lane = threadIdx.x & 31;
    const int nwarps = gridDim.x * (blockDim.x >> 5);
    const float4 w = (reinterpret_cast<const float4*>(W) + 32)[lane];   // W[128:256]
    stream_rows4<false>(feats, w, 0.0f, g_iscore, N, warp, nwarps, lane);
}

// ---------------------------------------------------------------------------
// Edge pass 1: out[e] = u[src[e]]  (grid-stride, co-resident with node_i)
// ---------------------------------------------------------------------------
__global__ void edge_u_kernel(const int2* __restrict__ src2,
                              const int* __restrict__ src_idx,
                              float* __restrict__ out, int E2, int E)
{
    const int tid = blockIdx.x * blockDim.x + threadIdx.x;
    const int nt  = gridDim.x * blockDim.x;
    float2* o2 = reinterpret_cast<float2*>(out);
    for (int i = tid; i < E2; i += nt) {
        const int2 s = src2[i];
        float2 r;
        r.x = g_uscore[s.x];
        r.y = g_uscore[s.y];
        o2[i] = r;
    }
    if (tid == 0 && (E & 1))
        out[E - 1] = g_uscore[src_idx[E - 1]];
}

// ---------------------------------------------------------------------------
// Edge pass 2: out[e] += i[dst[e]]  (one-shot; out re-read hits L2)
// ---------------------------------------------------------------------------
__global__ void edge_add_kernel(const int2* __restrict__ dst2,
                                const int* __restrict__ dst_idx,
                                float* __restrict__ out, int E2, int E)
{
    const int i = blockIdx.x * blockDim.x + threadIdx.x;
    if (i < E2) {
        const int2 d = dst2[i];
        float2* o2 = reinterpret_cast<float2*>(out);
        float2 r = o2[i];
        r.x += g_iscore[d.x];
        r.y += g_iscore[d.y];
        o2[i] = r;
    }
    if (i == 0 && (E & 1))
        out[E - 1] += g_iscore[dst_idx[E - 1]];
}

// ---------------------------------------------------------------------------
// Graph: nodeU ──┬─ edgeU(296 blk) ───┬─ edgeAdd
//                └─ nodeI(296 blk, side stream) ──┘
// Both middle kernels are half-machine grids -> co-resident overlap.
// ---------------------------------------------------------------------------
extern "C" void kernel_launch(void* const* d_in, const int* in_sizes, int n_in,
                              void* d_out, int out_size)
{
    const float* user_feats = (const float*)d_in[0];
    const float* item_feats = (const float*)d_in[1];
    const int*   src_idx    = (const int*)d_in[2];
    const int*   dst_idx    = (const int*)d_in[3];
    const float* W          = (const float*)d_in[4];
    const float* b          = (const float*)d_in[5];
    float*       out        = (float*)d_out;

    const int Nu = in_sizes[0] / 128;
    const int Ni = in_sizes[1] / 128;
    const int E  = in_sizes[2];
    const int E2 = E / 2;

    static cudaStream_t s_side = nullptr;
    static cudaEvent_t  e_fork = nullptr, e_join = nullptr;
    if (s_side == nullptr) {
        cudaStreamCreateWithFlags(&s_side, cudaStreamNonBlocking);
        cudaEventCreateWithFlags(&e_fork, cudaEventDisableTiming);
        cudaEventCreateWithFlags(&e_join, cudaEventDisableTiming);
    }

    // 1) nodeU: full machine, 4 rows/warp, 8 warps/block -> 32 rows/block.
    {
        const int blocks = (Nu + 31) / 32;
        node_u_kernel<<<blocks, 256, 0, 0>>>(user_feats, W, b, Nu);
    }

    if (s_side && e_fork && e_join) {
        // 2) fork: nodeI on side stream, half-machine grid (co-resident).
        cudaEventRecord(e_fork, 0);
        cudaStreamWaitEvent(s_side, e_fork, 0);
        node_i_kernel<<<296, 256, 0, s_side>>>(item_feats, W, Ni);
        cudaEventRecord(e_join, s_side);

        // 3) edgeU on main stream, half-machine grid (overlaps nodeI).
        edge_u_kernel<<<296, 256, 0, 0>>>((const int2*)src_idx, src_idx, out, E2, E);

        // 4) join, then edgeAdd one-shot.
        cudaStreamWaitEvent(0, e_join, 0);
        const int ablocks = (E2 + 255) / 256;
        edge_add_kernel<<<ablocks, 256, 0, 0>>>((const int2*)dst_idx, dst_idx, out, E2, E);
    } else {
        node_i_kernel<<<296, 256, 0, 0>>>(item_feats, W, Ni);
        edge_u_kernel<<<296, 256, 0, 0>>>((const int2*)src_idx, src_idx, out, E2, E);
        const int ablocks = (E2 + 255) / 256;
        edge_add_kernel<<<ablocks, 256, 0, 0>>>((const int2*)dst_idx, dst_idx, out, E2, E);
    }
}